// round 17
// baseline (speedup 1.0000x reference)
#include <cuda_runtime.h>
#include <cuda_bf16.h>
#include <cstdint>

// Problem constants
#define B  4
#define C  64
#define H  128
#define W  128
#define O  64
#define KH 3
#define KW 3
#define K  9
#define HW (H*W)      // 16384
#define NPIX (B*HW)   // 65536

#define GPX 128           // pixels per CTA (one image row)
#define NTILES (NPIX/GPX) // 512
#define NCH 9             // one chunk per tap k (64 channels)
#define NT 256

// ---- smem layout (bytes); XOR-swizzled 128B rows, no padding ----
// A: 2 buffers x (hi 16384 + lo 16384)
#define ABUF   32768
#define A_HI(buf) ((buf) * ABUF)
#define A_LO(buf) ((buf) * ABUF + 16384)
// W: 2 buffers x (hi 8192 + lo 8192)
#define SWB    65536
#define W_HI(buf) (SWB + (buf) * 16384)
#define W_LO(buf) (SWB + (buf) * 16384 + 8192)
// producer param scratch: 4 warps x 768B
#define SPS    98304
#define SME_TOT (SPS + 4 * 768)   // 101376

// named barrier ids
#define BAR_FULL0  1
#define BAR_FULL1  2
#define BAR_EMPTY0 3
#define BAR_EMPTY1 4
#define BAR_CONS   5

// Scratch (__device__ globals per allocation rules)
__device__ float          g_xt[B * HW * C];   // NHWC input fp32, 16.8MB
__device__ __nv_bfloat16  g_wh[K * O * C];    // weight hi, [k][o][c]
__device__ __nv_bfloat16  g_wl[K * O * C];    // weight lo

// ---------------- PTX helpers ----------------
__device__ __forceinline__ uint32_t smem_u32(const void* p) {
    uint32_t a;
    asm("{ .reg .u64 t; cvta.to.shared.u64 t, %1; cvt.u32.u64 %0, t; }" : "=r"(a) : "l"(p));
    return a;
}
__device__ __forceinline__ void ldsm_x4(uint32_t* r, uint32_t addr) {
    asm volatile("ldmatrix.sync.aligned.m8n8.x4.shared.b16 {%0,%1,%2,%3}, [%4];"
        : "=r"(r[0]), "=r"(r[1]), "=r"(r[2]), "=r"(r[3]) : "r"(addr));
}
__device__ __forceinline__ void ldsm_x2(uint32_t* r, uint32_t addr) {
    asm volatile("ldmatrix.sync.aligned.m8n8.x2.shared.b16 {%0,%1}, [%2];"
        : "=r"(r[0]), "=r"(r[1]) : "r"(addr));
}
__device__ __forceinline__ void mma16816(float* d, const uint32_t* a, const uint32_t* b) {
    asm volatile("mma.sync.aligned.m16n8k16.row.col.f32.bf16.bf16.f32 "
        "{%0,%1,%2,%3}, {%4,%5,%6,%7}, {%8,%9}, {%0,%1,%2,%3};"
        : "+f"(d[0]), "+f"(d[1]), "+f"(d[2]), "+f"(d[3])
        : "r"(a[0]), "r"(a[1]), "r"(a[2]), "r"(a[3]), "r"(b[0]), "r"(b[1]));
}
__device__ __forceinline__ void cp16(uint32_t saddr, const void* gptr) {
    asm volatile("cp.async.cg.shared.global [%0], [%1], 16;" :: "r"(saddr), "l"(gptr));
}
__device__ __forceinline__ void bar_sync(int id, int cnt) {
    asm volatile("bar.sync %0, %1;" :: "r"(id), "r"(cnt) : "memory");
}
__device__ __forceinline__ void bar_arrive(int id, int cnt) {
    asm volatile("bar.arrive %0, %1;" :: "r"(id), "r"(cnt) : "memory");
}

// ---------------------------------------------------------------------------
// Kernel A: NCHW -> NHWC transpose (fp32, sampler input)
// ---------------------------------------------------------------------------
__global__ void transpose_kernel(const float* __restrict__ x) {
    __shared__ float tile[32][33];
    int b  = blockIdx.z;
    int c0 = blockIdx.y * 32;
    int s0 = blockIdx.x * 32;
    int tx = threadIdx.x, ty = threadIdx.y;   // block (32, 8)
    #pragma unroll
    for (int i = 0; i < 32; i += 8)
        tile[ty + i][tx] = x[(b * C + c0 + ty + i) * HW + s0 + tx];
    __syncthreads();
    #pragma unroll
    for (int i = 0; i < 32; i += 8)
        g_xt[(b * HW + s0 + ty + i) * C + c0 + tx] = tile[tx][ty + i];
}

// ---------------------------------------------------------------------------
// Kernel B: weight split+repack  W[o][c][k] -> Wh/Wl [k][o][c] bf16
// ---------------------------------------------------------------------------
__global__ void wsplit_kernel(const float* __restrict__ w) {
    int idx = blockIdx.x * 256 + threadIdx.x;
    if (idx < K * O * C) {
        int k = idx >> 12;
        int o = (idx >> 6) & 63;
        int c = idx & 63;
        float v = w[(o * C + c) * K + k];
        __nv_bfloat16 hi = __float2bfloat16(v);
        __nv_bfloat16 lo = __float2bfloat16(v - __bfloat162float(hi));
        g_wh[idx] = hi;
        g_wl[idx] = lo;
    }
}

// ---------------------------------------------------------------------------
// Fused warp-specialized kernel. CTA = one image row (128 px) x 64 o.
//   Warps 0-3: producers — per tap, sample 128px x 64c into A[buf] (bf16 hi/lo)
//   Warps 4-7: consumers — HMMA 3-term from A[buf] + double-buffered W
//   Handshake: named barriers (FULL/EMPTY per buffer), A double-buffered.
//   R16 fix: consumer-wide barrier BEFORE issueW(ch+2) — the prefetch
//   overwrites W[(ch+2)&1] == W[ch&1], which lagging consumer warps may
//   still be reading (this race caused rel_err 2.5e-2).
// ---------------------------------------------------------------------------
__global__ __launch_bounds__(NT, 2)
void fused_ws_kernel(const float* __restrict__ offset,
                     const float* __restrict__ mask,
                     const float* __restrict__ bias,
                     float* __restrict__ out) {
    extern __shared__ char smem[];
    const uint32_t sb = smem_u32(smem);
    const int tid  = threadIdx.x;
    const int wid  = tid >> 5;
    const int lane = tid & 31;
    const int tile = blockIdx.x;
    const int b    = tile >> 7;
    const int row  = tile & 127;

    if (wid < 4) {
        // =================== PRODUCER ===================
        const int pw   = wid;
        const int px0  = pw * 32;
        const float* xb = g_xt + b * HW * C;
        const int coff = lane * 2;
        // per-warp param scratch
        int*   p_y0  = (int*)  (smem + SPS + pw * 768);
        int*   p_x0  = p_y0 + 32;
        float* p_w00 = (float*)(p_x0 + 32);
        float* p_w01 = p_w00 + 32;
        float* p_w10 = p_w01 + 32;
        float* p_w11 = p_w10 + 32;

        #pragma unroll 1
        for (int ch = 0; ch < NCH; ch++) {
            const int buf = ch & 1;
            if (ch >= 2) bar_sync(BAR_EMPTY0 + buf, NT);

            // params for this warp's 32 px (coalesced loads, lane = px)
            {
                int px = px0 + lane;
                float offy = offset[((b * 2 * K + 2 * ch    ) * H + row) * W + px];
                float offx = offset[((b * 2 * K + 2 * ch + 1) * H + row) * W + px];
                float m    = mask  [((b * K + ch) * H + row) * W + px];
                float py = offy + (float)(ch / KW) + (float)(row - 1);
                float pxf = offx + (float)(ch % KW) + (float)(px - 1);
                float y0f = floorf(py), x0f = floorf(pxf);
                float ly = py - y0f, lx = pxf - x0f;
                p_y0[lane] = (int)y0f;
                p_x0[lane] = (int)x0f;
                p_w00[lane] = (1.f - ly) * (1.f - lx) * m;
                p_w01[lane] = (1.f - ly) * lx * m;
                p_w10[lane] = ly * (1.f - lx) * m;
                p_w11[lane] = ly * lx * m;
            }
            __syncwarp();

            #pragma unroll 4
            for (int j = 0; j < 32; j++) {
                int px = px0 + j;
                int y0 = p_y0[j];
                int x0 = p_x0[j];
                float w00 = p_w00[j], w01 = p_w01[j], w10 = p_w10[j], w11 = p_w11[j];

                bool yv0 = (unsigned)y0 < H;
                bool yv1 = (unsigned)(y0 + 1) < H;
                bool xv0 = (unsigned)x0 < W;
                bool xv1 = (unsigned)(x0 + 1) < W;

                float2 v00 = {0.f, 0.f}, v01 = {0.f, 0.f}, v10 = {0.f, 0.f}, v11 = {0.f, 0.f};
                if (yv0 && xv0) v00 = *(const float2*)(xb + ((y0    ) * W + x0    ) * C + coff);
                if (yv0 && xv1) v01 = *(const float2*)(xb + ((y0    ) * W + x0 + 1) * C + coff);
                if (yv1 && xv0) v10 = *(const float2*)(xb + ((y0 + 1) * W + x0    ) * C + coff);
                if (yv1 && xv1) v11 = *(const float2*)(xb + ((y0 + 1) * W + x0 + 1) * C + coff);

                float rx = w00 * v00.x + w01 * v01.x + w10 * v10.x + w11 * v11.x;
                float ry = w00 * v00.y + w01 * v01.y + w10 * v10.y + w11 * v11.y;

                __nv_bfloat16 hx = __float2bfloat16(rx);
                __nv_bfloat16 hy = __float2bfloat16(ry);
                __nv_bfloat16 lx2 = __float2bfloat16(rx - __bfloat162float(hx));
                __nv_bfloat16 ly2 = __float2bfloat16(ry - __bfloat162float(hy));

                // swizzled store: row px, chunk = lane>>2, chunk ^= (px&7)
                uint32_t byte = px * 128 + ((((lane >> 2) ^ (px & 7)) << 4) | ((lane & 3) * 4));
                *(__nv_bfloat162*)(smem + A_HI(buf) + byte) = __nv_bfloat162(hx, hy);
                *(__nv_bfloat162*)(smem + A_LO(buf) + byte) = __nv_bfloat162(lx2, ly2);
            }
            bar_arrive(BAR_FULL0 + buf, NT);
        }
    } else {
        // =================== CONSUMER ===================
        const int cw   = wid - 4;
        const int px0  = cw * 32;
        const int ctid = tid & 127;

        const uint4* wh4 = (const uint4*)g_wh;
        const uint4* wl4 = (const uint4*)g_wl;
        // weight staging: 512 uint4 per plane, 128 threads -> 4 each
        auto issueW = [&](int ch) {
            size_t gbase = (size_t)ch * 512;
            #pragma unroll
            for (int j = 0; j < 4; j++) {
                int e = j * 128 + ctid;                 // 0..511
                int o = e >> 3;
                uint32_t byte = o * 128 + (((e & 7) ^ (o & 7)) << 4);
                cp16(sb + W_HI(ch & 1) + byte, wh4 + gbase + e);
                cp16(sb + W_LO(ch & 1) + byte, wl4 + gbase + e);
            }
            asm volatile("cp.async.commit_group;" ::: "memory");
        };
        issueW(0);
        issueW(1);

        float acc[2][8][4];
        #pragma unroll
        for (int i = 0; i < 2; i++)
            #pragma unroll
            for (int j = 0; j < 8; j++)
                #pragma unroll
                for (int r = 0; r < 4; r++) acc[i][j][r] = 0.f;

        // A fragment addressing (swizzled)
        const uint32_t arow   = px0 + (lane & 15);
        const uint32_t arowb  = arow * 128;
        const uint32_t axor   = lane & 7;
        const uint32_t achsel = lane >> 4;
        // B fragment addressing
        const uint32_t browb  = (lane & 7) * 128;
        const uint32_t bchsel = (lane >> 3) & 1;

        #pragma unroll 1
        for (int ch = 0; ch < NCH; ch++) {
            const int buf = ch & 1;
            bar_sync(BAR_FULL0 + buf, NT);            // A[buf] ready
            if (ch + 1 < NCH)
                asm volatile("cp.async.wait_group 1;" ::: "memory");
            else
                asm volatile("cp.async.wait_group 0;" ::: "memory");
            bar_sync(BAR_CONS, 128);                  // W visibility across consumer warps

            const uint32_t aHb = sb + A_HI(buf);
            const uint32_t aLb = sb + A_LO(buf);
            const uint32_t bHb = sb + W_HI(buf);
            const uint32_t bLb = sb + W_LO(buf);

            #pragma unroll
            for (int s = 0; s < 4; s++) {
                uint32_t ah[2][4], al[2][4];
                #pragma unroll
                for (int mt = 0; mt < 2; mt++) {
                    uint32_t off = arowb + mt * 2048 + ((((s * 2 + achsel) ^ axor) << 4));
                    ldsm_x4(ah[mt], aHb + off);
                    ldsm_x4(al[mt], aLb + off);
                }
                #pragma unroll
                for (int nt = 0; nt < 8; nt++) {
                    uint32_t boff = browb + nt * 1024 + ((((s * 2 + bchsel) ^ (lane & 7)) << 4));
                    uint32_t bh[2], bl[2];
                    ldsm_x2(bh, bHb + boff);
                    ldsm_x2(bl, bLb + boff);
                    #pragma unroll
                    for (int mt = 0; mt < 2; mt++) {
                        mma16816(acc[mt][nt], ah[mt], bh);
                        mma16816(acc[mt][nt], al[mt], bh);
                        mma16816(acc[mt][nt], ah[mt], bl);
                    }
                }
            }
            // R16 FIX: all consumer warps must be done reading W[buf] before
            // any warp's issueW(ch+2) overwrites it (same physical buffer).
            bar_sync(BAR_CONS, 128);
            bar_arrive(BAR_EMPTY0 + buf, NT);
            if (ch + 2 < NCH) issueW(ch + 2);
        }

        // ---- epilogue: D[px][o]
        const int hw0 = (tile << 7) & (HW - 1);
        float* ob = out + (size_t)b * O * HW + hw0;
        #pragma unroll
        for (int nt = 0; nt < 8; nt++) {
            int o_b = nt * 8 + (lane & 3) * 2;
            float bv0 = __ldg(&bias[o_b]);
            float bv1 = __ldg(&bias[o_b + 1]);
            #pragma unroll
            for (int mt = 0; mt < 2; mt++) {
                int px = px0 + mt * 16 + (lane >> 2);
                float* p0 = ob + (size_t)o_b * HW + px;
                p0[0]      = acc[mt][nt][0] + bv0;
                p0[HW]     = acc[mt][nt][1] + bv1;
                p0[8]      = acc[mt][nt][2] + bv0;
                p0[HW + 8] = acc[mt][nt][3] + bv1;
            }
        }
    }
}

// ---------------------------------------------------------------------------
extern "C" void kernel_launch(void* const* d_in, const int* in_sizes, int n_in,
                              void* d_out, int out_size) {
    const float* x      = (const float*)d_in[0];
    const float* offset = (const float*)d_in[1];
    const float* mask   = (const float*)d_in[2];
    const float* weight = (const float*)d_in[3];
    const float* bias   = (const float*)d_in[4];
    float* out = (float*)d_out;

    {   // A: transpose to NHWC
        dim3 grid(HW / 32, C / 32, B);
        dim3 block(32, 8);
        transpose_kernel<<<grid, block>>>(x);
    }
    {   // B: weight split/repack
        wsplit_kernel<<<(K * O * C + 255) / 256, 256>>>(weight);
    }
    {   // C: fused warp-specialized sample + HMMA
        cudaFuncSetAttribute(fused_ws_kernel,
                             cudaFuncAttributeMaxDynamicSharedMemorySize, SME_TOT);
        fused_ws_kernel<<<NTILES, NT, SME_TOT>>>(offset, mask, bias, out);
    }
}